// round 11
// baseline (speedup 1.0000x reference)
#include <cuda_runtime.h>
#include <cuda_bf16.h>
#include <cstdint>

#define TOKENS 8192
#define DM     1024
#define LSEQ   2048
#define NB     4
#define NH     16
#define DK     64

// Scratch (device globals — no allocation in kernel_launch)
__device__ float g_qkv[(size_t)TOKENS * 3 * DM]; // qkv (rope applied in-place)
__device__ __nv_bfloat16 g_hh[TOKENS * DM];      // layernorm out hi
__device__ __nv_bfloat16 g_hl[TOKENS * DM];      // layernorm out lo
__device__ __nv_bfloat16 g_wih[3 * DM * DM];     // W_in hi
__device__ __nv_bfloat16 g_wil[3 * DM * DM];     // W_in lo
__device__ __nv_bfloat16 g_woh[DM * DM];         // W_o hi
__device__ __nv_bfloat16 g_wol[DM * DM];         // W_o lo
__device__ __nv_bfloat16 g_oh[TOKENS * DM];      // attention out hi
__device__ __nv_bfloat16 g_ol[TOKENS * DM];      // attention out lo

// ===========================================================================
// Helpers
// ===========================================================================
__device__ __forceinline__ void mma_bf16(float* c, const uint32_t* a,
                                         const uint32_t* b) {
    asm volatile(
        "mma.sync.aligned.m16n8k16.row.col.f32.bf16.bf16.f32 "
        "{%0,%1,%2,%3}, {%4,%5,%6,%7}, {%8,%9}, {%0,%1,%2,%3};\n"
        : "+f"(c[0]), "+f"(c[1]), "+f"(c[2]), "+f"(c[3])
        : "r"(a[0]), "r"(a[1]), "r"(a[2]), "r"(a[3]), "r"(b[0]), "r"(b[1]));
}
__device__ __forceinline__ uint32_t pack2(__nv_bfloat16 lo, __nv_bfloat16 hi) {
    __nv_bfloat162 t = __halves2bfloat162(lo, hi);
    return *reinterpret_cast<uint32_t*>(&t);
}
__device__ __forceinline__ uint32_t smem_u32addr(const void* p) {
    uint32_t a;
    asm("{ .reg .u64 t; cvta.to.shared.u64 t, %1; cvt.u32.u64 %0, t; }"
        : "=r"(a) : "l"(p));
    return a;
}
__device__ __forceinline__ void ldmx4(uint32_t& r0, uint32_t& r1,
                                      uint32_t& r2, uint32_t& r3,
                                      uint32_t addr) {
    asm volatile(
        "ldmatrix.sync.aligned.m8n8.x4.shared.b16 {%0,%1,%2,%3}, [%4];"
        : "=r"(r0), "=r"(r1), "=r"(r2), "=r"(r3) : "r"(addr));
}
__device__ __forceinline__ void ldmx4t(uint32_t& r0, uint32_t& r1,
                                       uint32_t& r2, uint32_t& r3,
                                       uint32_t addr) {
    asm volatile(
        "ldmatrix.sync.aligned.m8n8.x4.trans.shared.b16 {%0,%1,%2,%3}, [%4];"
        : "=r"(r0), "=r"(r1), "=r"(r2), "=r"(r3) : "r"(addr));
}
__device__ __forceinline__ void split4(float4 v, uint32_t& h0, uint32_t& h1,
                                       uint32_t& l0, uint32_t& l1) {
    __nv_bfloat16 hx = __float2bfloat16_rn(v.x);
    __nv_bfloat16 hy = __float2bfloat16_rn(v.y);
    __nv_bfloat16 hz = __float2bfloat16_rn(v.z);
    __nv_bfloat16 hw = __float2bfloat16_rn(v.w);
    h0 = pack2(hx, hy); h1 = pack2(hz, hw);
    l0 = pack2(__float2bfloat16_rn(v.x - __bfloat162float(hx)),
               __float2bfloat16_rn(v.y - __bfloat162float(hy)));
    l1 = pack2(__float2bfloat16_rn(v.z - __bfloat162float(hz)),
               __float2bfloat16_rn(v.w - __bfloat162float(hw)));
}

// ===========================================================================
// LayerNorm: one block per row, writes bf16 hi/lo split directly
// ===========================================================================
__global__ __launch_bounds__(256) void ln_kernel(const float* __restrict__ x,
                                                 __nv_bfloat16* __restrict__ hh,
                                                 __nv_bfloat16* __restrict__ hl) {
    int row = blockIdx.x;
    int t = threadIdx.x;
    const float4* xr = (const float4*)(x + (size_t)row * DM);
    float4 v = xr[t];
    float s  = v.x + v.y + v.z + v.w;
    float ss = v.x * v.x + v.y * v.y + v.z * v.z + v.w * v.w;
    #pragma unroll
    for (int off = 16; off; off >>= 1) {
        s  += __shfl_xor_sync(0xffffffffu, s, off);
        ss += __shfl_xor_sync(0xffffffffu, ss, off);
    }
    __shared__ float sh[16];
    __shared__ float sh_mu, sh_r;
    int warp = t >> 5, lane = t & 31;
    if (lane == 0) { sh[warp] = s; sh[warp + 8] = ss; }
    __syncthreads();
    if (t == 0) {
        float S = 0.f, SS = 0.f;
        #pragma unroll
        for (int w = 0; w < 8; w++) { S += sh[w]; SS += sh[w + 8]; }
        float mu  = S * (1.0f / DM);
        float var = SS * (1.0f / DM) - mu * mu;
        sh_mu = mu;
        sh_r  = rsqrtf(var + 1e-8f);
    }
    __syncthreads();
    float mu = sh_mu, r = sh_r;
    float4 o = make_float4((v.x - mu) * r, (v.y - mu) * r,
                           (v.z - mu) * r, (v.w - mu) * r);
    uint32_t h0, h1, l0, l1;
    split4(o, h0, h1, l0, l1);
    uint32_t* hw = (uint32_t*)(hh + (size_t)row * DM);
    uint32_t* lw = (uint32_t*)(hl + (size_t)row * DM);
    hw[2 * t] = h0; hw[2 * t + 1] = h1;
    lw[2 * t] = l0; lw[2 * t + 1] = l1;
}

// ===========================================================================
// Weight split: fp32 -> bf16 hi/lo
// ===========================================================================
__global__ __launch_bounds__(256) void split_kernel(const float* __restrict__ src,
                                                    __nv_bfloat16* __restrict__ hi,
                                                    __nv_bfloat16* __restrict__ lo,
                                                    int n4) {
    int i = blockIdx.x * blockDim.x + threadIdx.x;
    if (i >= n4) return;
    float4 v = ((const float4*)src)[i];
    uint32_t h0, h1, l0, l1;
    split4(v, h0, h1, l0, l1);
    ((uint32_t*)hi)[2 * i] = h0; ((uint32_t*)hi)[2 * i + 1] = h1;
    ((uint32_t*)lo)[2 * i] = l0; ((uint32_t*)lo)[2 * i + 1] = l1;
}

// ===========================================================================
// Split-bf16 NT GEMM, pre-split bf16 inputs, ldmatrix fragment loads.
// C[M,N] = (Ah+Al)(Bh+Bl)^T with 3 products. 128x128 tile, BK=16, 8 warps.
// Smem rows: 16 bf16 = 8 u32 data, padded to 12 u32 (48B) -> conflict-free
// ldmatrix (verified bank pattern).
// ===========================================================================
#define BM 128
#define BN 128
#define SROW 12
#define SARR (BM * SROW)              // 1536 u32
#define SSTAGE (4 * SARR)
#define GEMM_SMEM (2 * SSTAGE * 4)    // 49152 B

__global__ __launch_bounds__(256) void gemm_bf(
    const __nv_bfloat16* __restrict__ Ah, const __nv_bfloat16* __restrict__ Al,
    const __nv_bfloat16* __restrict__ Bh, const __nv_bfloat16* __restrict__ Bl,
    float* __restrict__ C, int M, int N_, int K) {
    extern __shared__ uint32_t smu[];
    int t = threadIdx.x;
    int lane = t & 31, wid = t >> 5;
    int wm = wid >> 2, wn = wid & 3;
    int g = lane >> 2, t4 = lane & 3;
    int m0 = blockIdx.y * BM, n0 = blockIdx.x * BN;

    float acc[4][4][4];
    #pragma unroll
    for (int i = 0; i < 4; i++)
        #pragma unroll
        for (int j = 0; j < 4; j++)
            #pragma unroll
            for (int q = 0; q < 4; q++) acc[i][j][q] = 0.f;

    // global load: thread -> row t>>1, k-half t&1 (8 bf16 = 16B each)
    int lrow = t >> 1, lhalf = t & 1;
    int sidx = lrow * SROW + lhalf * 4;
    const size_t aoff = (size_t)(m0 + lrow) * K + lhalf * 8;
    const size_t boff = (size_t)(n0 + lrow) * K + lhalf * 8;

    const int NST = K / 16;
    uint4 pah, pal, pbh, pbl;
    pah = *(const uint4*)(Ah + aoff);
    pal = *(const uint4*)(Al + aoff);
    pbh = *(const uint4*)(Bh + boff);
    pbl = *(const uint4*)(Bl + boff);

    // ldmatrix lane byte offsets
    int r8 = lane & 7, mat = lane >> 3;
    int a_loff = ((wm * 64 + (mat & 1) * 8 + r8) * SROW + (mat >> 1) * 4) * 4;
    int b_loff = ((wn * 32 + (mat >> 1) * 8 + r8) * SROW + (mat & 1) * 4) * 4;
    uint32_t sbase = smem_u32addr(smu);

    for (int s = 0; s < NST; s++) {
        uint32_t* Sb = smu + (s & 1) * SSTAGE;
        *(uint4*)(Sb + sidx)            = pah;
        *(uint4*)(Sb + SARR + sidx)     = pal;
        *(uint4*)(Sb + 2 * SARR + sidx) = pbh;
        *(uint4*)(Sb + 3 * SARR + sidx) = pbl;
        __syncthreads();

        if (s + 1 < NST) {
            int k0 = (s + 1) * 16;
            pah = *(const uint4*)(Ah + aoff + k0);
            pal = *(const uint4*)(Al + aoff + k0);
            pbh = *(const uint4*)(Bh + boff + k0);
            pbl = *(const uint4*)(Bl + boff + k0);
        }

        uint32_t stb = sbase + (s & 1) * (SSTAGE * 4);
        uint32_t ah[4][4], al[4][4], bh[4][2], bl[4][2];
        #pragma unroll
        for (int mb = 0; mb < 4; mb++) {
            ldmx4(ah[mb][0], ah[mb][1], ah[mb][2], ah[mb][3],
                  stb + a_loff + mb * (16 * SROW * 4));
            ldmx4(al[mb][0], al[mb][1], al[mb][2], al[mb][3],
                  stb + SARR * 4 + a_loff + mb * (16 * SROW * 4));
        }
        #pragma unroll
        for (int p = 0; p < 2; p++) {
            ldmx4(bh[2 * p][0], bh[2 * p][1], bh[2 * p + 1][0], bh[2 * p + 1][1],
                  stb + 2 * SARR * 4 + b_loff + p * (16 * SROW * 4));
            ldmx4(bl[2 * p][0], bl[2 * p][1], bl[2 * p + 1][0], bl[2 * p + 1][1],
                  stb + 3 * SARR * 4 + b_loff + p * (16 * SROW * 4));
        }
        #pragma unroll
        for (int mb = 0; mb < 4; mb++)
            #pragma unroll
            for (int nb = 0; nb < 4; nb++) {
                mma_bf16(acc[mb][nb], ah[mb], bh[nb]);
                mma_bf16(acc[mb][nb], ah[mb], bl[nb]);
                mma_bf16(acc[mb][nb], al[mb], bh[nb]);
            }
        __syncthreads();
    }

    #pragma unroll
    for (int mb = 0; mb < 4; mb++) {
        int row = m0 + wm * 64 + mb * 16 + g;
        #pragma unroll
        for (int nb = 0; nb < 4; nb++) {
            int col = n0 + wn * 32 + nb * 8 + 2 * t4;
            *(float2*)(C + (size_t)row * N_ + col) =
                make_float2(acc[mb][nb][0], acc[mb][nb][1]);
            *(float2*)(C + (size_t)(row + 8) * N_ + col) =
                make_float2(acc[mb][nb][2], acc[mb][nb][3]);
        }
    }
}

// ===========================================================================
// RoPE (unchanged)
// ===========================================================================
__global__ __launch_bounds__(512) void rope_kernel(float* __restrict__ qkv) {
    int token = blockIdx.x;
    int p = threadIdx.x;
    int head = p >> 5;
    int i = p & 31;
    int l = token & (LSEQ - 1);
    double inv = pow(10000.0, -(double)i / 32.0);
    double ang = (double)l * inv;
    double snd, csd;
    sincos(ang, &snd, &csd);
    float sn = (float)snd, cs = (float)csd;
    size_t base = (size_t)token * 3 * DM + head * DK + 2 * i;
    float x1 = qkv[base], x2 = qkv[base + 1];
    qkv[base]     = x1 * cs - x2 * sn;
    qkv[base + 1] = x1 * sn + x2 * cs;
    float y1 = qkv[base + DM], y2 = qkv[base + DM + 1];
    qkv[base + DM]     = y1 * cs - y2 * sn;
    qkv[base + DM + 1] = y1 * sn + y2 * cs;
}

// ===========================================================================
// Tensor-core causal flash attention (split-bf16 mma.sync, FA2-style).
// Epilogue writes bf16 hi/lo split for the out-projection GEMM.
// ===========================================================================
#define FQ 128
#define FK 64
#define FR 36
#define OQH 0
#define OQL (FQ * FR)
#define OKH (2 * FQ * FR)
#define OKL (OKH + FK * FR)
#define OVH (OKH + 2 * FK * FR)
#define OVL (OVH + FK * FR)
#define FLASH_SMEM ((2 * FQ * FR + 4 * FK * FR) * 4)

__global__ __launch_bounds__(256) void flash_tc(const float* __restrict__ qkv,
                                                __nv_bfloat16* __restrict__ oh,
                                                __nv_bfloat16* __restrict__ ol) {
    extern __shared__ uint32_t su[];
    int t = threadIdx.x;
    int lane = t & 31, wq = t >> 5;
    int g = lane >> 2, t4 = lane & 3;
    int qt = (int)gridDim.x - 1 - (int)blockIdx.x;
    int h = blockIdx.y, b = blockIdx.z;
    int qbase = qt * FQ;

    {
        const float* qb = qkv + ((size_t)(b * LSEQ + qbase)) * 3 * DM + h * DK;
        #pragma unroll
        for (int it = 0; it < 8; it++) {
            int f = t + it * 256;
            int row = f >> 4, c4 = (f & 15);
            float4 v = *(const float4*)(qb + (size_t)row * 3 * DM + c4 * 4);
            uint32_t h0, h1, l0, l1;
            split4(v, h0, h1, l0, l1);
            int idx = row * FR + c4 * 2;
            su[OQH + idx] = h0; su[OQH + idx + 1] = h1;
            su[OQL + idx] = l0; su[OQL + idx + 1] = l1;
        }
    }
    __syncthreads();

    uint32_t qah[4][4], qal[4][4];
    #pragma unroll
    for (int s = 0; s < 4; s++) {
        int idx = (wq * 16 + g) * FR + 8 * s + t4;
        qah[s][0] = su[OQH + idx];          qah[s][1] = su[OQH + idx + 8 * FR];
        qah[s][2] = su[OQH + idx + 4];      qah[s][3] = su[OQH + idx + 8 * FR + 4];
        qal[s][0] = su[OQL + idx];          qal[s][1] = su[OQL + idx + 8 * FR];
        qal[s][2] = su[OQL + idx + 4];      qal[s][3] = su[OQL + idx + 8 * FR + 4];
    }

    float of[8][4];
    #pragma unroll
    for (int n = 0; n < 8; n++)
        #pragma unroll
        for (int c = 0; c < 4; c++) of[n][c] = 0.f;
    float m0 = -1e30f, m1 = -1e30f, l0 = 0.f, l1 = 0.f;

    uint32_t vbase_h = smem_u32addr(su + OVH);
    uint32_t vbase_l = smem_u32addr(su + OVL);
    int voff = ((lane & 15) * FR + (lane >> 4) * 4) * 4;

    int row0 = qbase + wq * 16 + g;
    int nkt = 2 * qt + 2;

    for (int kt = 0; kt < nkt; kt++) {
        {
            const float* kb = qkv + ((size_t)(b * LSEQ + kt * FK)) * 3 * DM + DM + h * DK;
            #pragma unroll
            for (int it = 0; it < 4; it++) {
                int f = t + it * 256;
                int row = f >> 4, c4 = (f & 15);
                int idx = row * FR + c4 * 2;
                float4 kv = *(const float4*)(kb + (size_t)row * 3 * DM + c4 * 4);
                uint32_t h0, h1, lo0, lo1;
                split4(kv, h0, h1, lo0, lo1);
                su[OKH + idx] = h0; su[OKH + idx + 1] = h1;
                su[OKL + idx] = lo0; su[OKL + idx + 1] = lo1;
                float4 vv = *(const float4*)(kb + DM + (size_t)row * 3 * DM + c4 * 4);
                split4(vv, h0, h1, lo0, lo1);
                su[OVH + idx] = h0; su[OVH + idx + 1] = h1;
                su[OVL + idx] = lo0; su[OVL + idx + 1] = lo1;
            }
        }
        __syncthreads();

        int ktb = kt * FK;
        bool active = (ktb <= qbase + wq * 16);
        if (active) {
            float sf[8][4];
            #pragma unroll
            for (int j = 0; j < 8; j++)
                #pragma unroll
                for (int c = 0; c < 4; c++) sf[j][c] = 0.f;
            #pragma unroll
            for (int s = 0; s < 4; s++) {
                #pragma unroll
                for (int j = 0; j < 8; j++) {
                    int idx = (8 * j + g) * FR + 8 * s + t4;
                    uint32_t kb2[2], kl2[2];
                    kb2[0] = su[OKH + idx]; kb2[1] = su[OKH + idx + 4];
                    kl2[0] = su[OKL + idx]; kl2[1] = su[OKL + idx + 4];
                    mma_bf16(sf[j], qah[s], kb2);
                    mma_bf16(sf[j], qal[s], kb2);
                    mma_bf16(sf[j], qah[s], kl2);
                }
            }

            const float scale = 0.125f;
            bool need_mask = (ktb + FK - 1 > qbase + wq * 16);
            #pragma unroll
            for (int j = 0; j < 8; j++) {
                int col = ktb + 8 * j + 2 * t4;
                #pragma unroll
                for (int c = 0; c < 4; c++) {
                    float v = sf[j][c] * scale;
                    if (need_mask) {
                        int cc = col + (c & 1);
                        int rr = row0 + (c >> 1) * 8;
                        if (cc > rr) v = -1e30f;
                    }
                    sf[j][c] = v;
                }
            }

            float mx0 = -1e30f, mx1 = -1e30f;
            #pragma unroll
            for (int j = 0; j < 8; j++) {
                mx0 = fmaxf(mx0, fmaxf(sf[j][0], sf[j][1]));
                mx1 = fmaxf(mx1, fmaxf(sf[j][2], sf[j][3]));
            }
            mx0 = fmaxf(mx0, __shfl_xor_sync(0xffffffffu, mx0, 1));
            mx0 = fmaxf(mx0, __shfl_xor_sync(0xffffffffu, mx0, 2));
            mx1 = fmaxf(mx1, __shfl_xor_sync(0xffffffffu, mx1, 1));
            mx1 = fmaxf(mx1, __shfl_xor_sync(0xffffffffu, mx1, 2));
            float mn0 = fmaxf(m0, mx0), mn1 = fmaxf(m1, mx1);
            float a0 = __expf(m0 - mn0), a1 = __expf(m1 - mn1);
            m0 = mn0; m1 = mn1;
            float s0 = 0.f, s1 = 0.f;
            #pragma unroll
            for (int j = 0; j < 8; j++) {
                sf[j][0] = __expf(sf[j][0] - m0);
                sf[j][1] = __expf(sf[j][1] - m0);
                sf[j][2] = __expf(sf[j][2] - m1);
                sf[j][3] = __expf(sf[j][3] - m1);
                s0 += sf[j][0] + sf[j][1];
                s1 += sf[j][2] + sf[j][3];
            }
            s0 += __shfl_xor_sync(0xffffffffu, s0, 1);
            s0 += __shfl_xor_sync(0xffffffffu, s0, 2);
            s1 += __shfl_xor_sync(0xffffffffu, s1, 1);
            s1 += __shfl_xor_sync(0xffffffffu, s1, 2);
            l0 = l0 * a0 + s0;
            l1 = l1 * a1 + s1;
            #pragma unroll
            for (int n = 0; n < 8; n++) {
                of[n][0] *= a0; of[n][1] *= a0;
                of[n][2] *= a1; of[n][3] *= a1;
            }

            #pragma unroll
            for (int s = 0; s < 4; s++) {
                uint32_t pah[4], pal[4];
                #pragma unroll
                for (int half = 0; half < 2; half++) {
                    float p0 = sf[2 * s + half][0], p1 = sf[2 * s + half][1];
                    float p2 = sf[2 * s + half][2], p3 = sf[2 * s + half][3];
                    __nv_bfloat16 h0 = __float2bfloat16_rn(p0);
                    __nv_bfloat16 h1b = __float2bfloat16_rn(p1);
                    __nv_bfloat16 h2 = __float2bfloat16_rn(p2);
                    __nv_bfloat16 h3 = __float2bfloat16_rn(p3);
                    pah[2 * half]     = pack2(h0, h1b);
                    pah[2 * half + 1] = pack2(h2, h3);
                    pal[2 * half]     = pack2(
                        __float2bfloat16_rn(p0 - __bfloat162float(h0)),
                        __float2bfloat16_rn(p1 - __bfloat162float(h1b)));
                    pal[2 * half + 1] = pack2(
                        __float2bfloat16_rn(p2 - __bfloat162float(h2)),
                        __float2bfloat16_rn(p3 - __bfloat162float(h3)));
                }
                #pragma unroll
                for (int j2 = 0; j2 < 4; j2++) {
                    uint32_t vh0, vh1, vh2, vh3, vl0, vl1, vl2, vl3;
                    uint32_t boff2 = (16 * s * FR + 8 * j2) * 4 + voff;
                    ldmx4t(vh0, vh1, vh2, vh3, vbase_h + boff2);
                    ldmx4t(vl0, vl1, vl2, vl3, vbase_l + boff2);
                    uint32_t bh0[2] = {vh0, vh1}, bh1[2] = {vh2, vh3};
                    uint32_t bl0[2] = {vl0, vl1}, bl1[2] = {vl2, vl3};
                    mma_bf16(of[2 * j2], pah, bh0);
                    mma_bf16(of[2 * j2], pal, bh0);
                    mma_bf16(of[2 * j2], pah, bl0);
                    mma_bf16(of[2 * j2 + 1], pah, bh1);
                    mma_bf16(of[2 * j2 + 1], pal, bh1);
                    mma_bf16(of[2 * j2 + 1], pah, bl1);
                }
            }
        }
        __syncthreads();
    }

    // ---- epilogue: write bf16 hi/lo split ----
    float i0 = 1.f / l0, i1 = 1.f / l1;
    size_t base0 = (size_t)(b * LSEQ + row0) * DM + h * DK;
    size_t base1 = base0 + 8 * DM;
    uint32_t* ohw = (uint32_t*)oh;
    uint32_t* olw = (uint32_t*)ol;
    #pragma unroll
    for (int n = 0; n < 8; n++) {
        int col = 8 * n + 2 * t4;
        float v0 = of[n][0] * i0, v1 = of[n][1] * i0;
        float v2 = of[n][2] * i1, v3 = of[n][3] * i1;
        __nv_bfloat16 h0 = __float2bfloat16_rn(v0);
        __nv_bfloat16 h1 = __float2bfloat16_rn(v1);
        __nv_bfloat16 h2 = __float2bfloat16_rn(v2);
        __nv_bfloat16 h3 = __float2bfloat16_rn(v3);
        ohw[(base0 + col) >> 1] = pack2(h0, h1);
        ohw[(base1 + col) >> 1] = pack2(h2, h3);
        olw[(base0 + col) >> 1] = pack2(
            __float2bfloat16_rn(v0 - __bfloat162float(h0)),
            __float2bfloat16_rn(v1 - __bfloat162float(h1)));
        olw[(base1 + col) >> 1] = pack2(
            __float2bfloat16_rn(v2 - __bfloat162float(h2)),
            __float2bfloat16_rn(v3 - __bfloat162float(h3)));
    }
}

// ===========================================================================
extern "C" void kernel_launch(void* const* d_in, const int* in_sizes, int n_in,
                              void* d_out, int out_size) {
    const float* x    = (const float*)d_in[0];
    const float* W_in = (const float*)d_in[1];
    const float* W_o  = (const float*)d_in[2];
    float* out = (float*)d_out;

    float* qkv;
    __nv_bfloat16 *hh, *hl, *wih, *wil, *woh, *wol, *oh, *ol;
    cudaGetSymbolAddress((void**)&qkv, g_qkv);
    cudaGetSymbolAddress((void**)&hh,  g_hh);
    cudaGetSymbolAddress((void**)&hl,  g_hl);
    cudaGetSymbolAddress((void**)&wih, g_wih);
    cudaGetSymbolAddress((void**)&wil, g_wil);
    cudaGetSymbolAddress((void**)&woh, g_woh);
    cudaGetSymbolAddress((void**)&wol, g_wol);
    cudaGetSymbolAddress((void**)&oh,  g_oh);
    cudaGetSymbolAddress((void**)&ol,  g_ol);

    cudaFuncSetAttribute(gemm_bf, cudaFuncAttributeMaxDynamicSharedMemorySize,
                         GEMM_SMEM);
    cudaFuncSetAttribute(flash_tc, cudaFuncAttributeMaxDynamicSharedMemorySize,
                         FLASH_SMEM);

    ln_kernel<<<TOKENS, 256>>>(x, hh, hl);
    split_kernel<<<(3 * DM * DM / 4 + 255) / 256, 256>>>(W_in, wih, wil,
                                                         3 * DM * DM / 4);
    split_kernel<<<(DM * DM / 4 + 255) / 256, 256>>>(W_o, woh, wol,
                                                     DM * DM / 4);

    dim3 g1(3 * DM / BN, TOKENS / BM);
    gemm_bf<<<g1, 256, GEMM_SMEM>>>(hh, hl, wih, wil, qkv, TOKENS, 3 * DM, DM);

    rope_kernel<<<TOKENS, 512>>>(qkv);

    dim3 g2(LSEQ / FQ, NH, NB);
    flash_tc<<<g2, 256, FLASH_SMEM>>>(qkv, oh, ol);

    dim3 g3(DM / BN, TOKENS / BM);
    gemm_bf<<<g3, 256, GEMM_SMEM>>>(oh, ol, woh, wol, out, TOKENS, DM, DM);
}

// round 12
// speedup vs baseline: 1.7367x; 1.7367x over previous
#include <cuda_runtime.h>
#include <cuda_bf16.h>
#include <cstdint>

#define TOKENS 8192
#define DM     1024
#define LSEQ   2048
#define NB     4
#define NH     16
#define DK     64

// Scratch (device globals — no allocation in kernel_launch)
__device__ float g_qkv[(size_t)TOKENS * 3 * DM]; // qkv (rope applied in-place)
__device__ __nv_bfloat16 g_hh[TOKENS * DM];      // layernorm out hi
__device__ __nv_bfloat16 g_hl[TOKENS * DM];      // layernorm out lo
__device__ __nv_bfloat16 g_wih[3 * DM * DM];     // W_in hi
__device__ __nv_bfloat16 g_wil[3 * DM * DM];     // W_in lo
__device__ __nv_bfloat16 g_woh[DM * DM];         // W_o hi
__device__ __nv_bfloat16 g_wol[DM * DM];         // W_o lo
__device__ __nv_bfloat16 g_oh[TOKENS * DM];      // attention out hi
__device__ __nv_bfloat16 g_ol[TOKENS * DM];      // attention out lo

// ===========================================================================
// Helpers
// ===========================================================================
__device__ __forceinline__ void mma_bf16(float* c, const uint32_t* a,
                                         const uint32_t* b) {
    asm volatile(
        "mma.sync.aligned.m16n8k16.row.col.f32.bf16.bf16.f32 "
        "{%0,%1,%2,%3}, {%4,%5,%6,%7}, {%8,%9}, {%0,%1,%2,%3};\n"
        : "+f"(c[0]), "+f"(c[1]), "+f"(c[2]), "+f"(c[3])
        : "r"(a[0]), "r"(a[1]), "r"(a[2]), "r"(a[3]), "r"(b[0]), "r"(b[1]));
}
__device__ __forceinline__ uint32_t pack2(__nv_bfloat16 lo, __nv_bfloat16 hi) {
    __nv_bfloat162 t = __halves2bfloat162(lo, hi);
    return *reinterpret_cast<uint32_t*>(&t);
}
__device__ __forceinline__ uint32_t smem_u32addr(const void* p) {
    uint32_t a;
    asm("{ .reg .u64 t; cvta.to.shared.u64 t, %1; cvt.u32.u64 %0, t; }"
        : "=r"(a) : "l"(p));
    return a;
}
__device__ __forceinline__ void ldmx4(uint32_t& r0, uint32_t& r1,
                                      uint32_t& r2, uint32_t& r3,
                                      uint32_t addr) {
    asm volatile(
        "ldmatrix.sync.aligned.m8n8.x4.shared.b16 {%0,%1,%2,%3}, [%4];"
        : "=r"(r0), "=r"(r1), "=r"(r2), "=r"(r3) : "r"(addr));
}
__device__ __forceinline__ void ldmx4t(uint32_t& r0, uint32_t& r1,
                                       uint32_t& r2, uint32_t& r3,
                                       uint32_t addr) {
    asm volatile(
        "ldmatrix.sync.aligned.m8n8.x4.trans.shared.b16 {%0,%1,%2,%3}, [%4];"
        : "=r"(r0), "=r"(r1), "=r"(r2), "=r"(r3) : "r"(addr));
}
__device__ __forceinline__ void cp16(uint32_t dst, const void* src) {
    asm volatile("cp.async.cg.shared.global [%0], [%1], 16;"
                 :: "r"(dst), "l"(src) : "memory");
}
#define CP_COMMIT() asm volatile("cp.async.commit_group;" ::: "memory")
#define CP_WAIT0()  asm volatile("cp.async.wait_group 0;" ::: "memory")

__device__ __forceinline__ void split4(float4 v, uint32_t& h0, uint32_t& h1,
                                       uint32_t& l0, uint32_t& l1) {
    __nv_bfloat16 hx = __float2bfloat16_rn(v.x);
    __nv_bfloat16 hy = __float2bfloat16_rn(v.y);
    __nv_bfloat16 hz = __float2bfloat16_rn(v.z);
    __nv_bfloat16 hw = __float2bfloat16_rn(v.w);
    h0 = pack2(hx, hy); h1 = pack2(hz, hw);
    l0 = pack2(__float2bfloat16_rn(v.x - __bfloat162float(hx)),
               __float2bfloat16_rn(v.y - __bfloat162float(hy)));
    l1 = pack2(__float2bfloat16_rn(v.z - __bfloat162float(hz)),
               __float2bfloat16_rn(v.w - __bfloat162float(hw)));
}

// ===========================================================================
// LayerNorm: one block per row, writes bf16 hi/lo split directly
// ===========================================================================
__global__ __launch_bounds__(256) void ln_kernel(const float* __restrict__ x,
                                                 __nv_bfloat16* __restrict__ hh,
                                                 __nv_bfloat16* __restrict__ hl) {
    int row = blockIdx.x;
    int t = threadIdx.x;
    const float4* xr = (const float4*)(x + (size_t)row * DM);
    float4 v = xr[t];
    float s  = v.x + v.y + v.z + v.w;
    float ss = v.x * v.x + v.y * v.y + v.z * v.z + v.w * v.w;
    #pragma unroll
    for (int off = 16; off; off >>= 1) {
        s  += __shfl_xor_sync(0xffffffffu, s, off);
        ss += __shfl_xor_sync(0xffffffffu, ss, off);
    }
    __shared__ float sh[16];
    __shared__ float sh_mu, sh_r;
    int warp = t >> 5, lane = t & 31;
    if (lane == 0) { sh[warp] = s; sh[warp + 8] = ss; }
    __syncthreads();
    if (t == 0) {
        float S = 0.f, SS = 0.f;
        #pragma unroll
        for (int w = 0; w < 8; w++) { S += sh[w]; SS += sh[w + 8]; }
        float mu  = S * (1.0f / DM);
        float var = SS * (1.0f / DM) - mu * mu;
        sh_mu = mu;
        sh_r  = rsqrtf(var + 1e-8f);
    }
    __syncthreads();
    float mu = sh_mu, r = sh_r;
    float4 o = make_float4((v.x - mu) * r, (v.y - mu) * r,
                           (v.z - mu) * r, (v.w - mu) * r);
    uint32_t h0, h1, l0, l1;
    split4(o, h0, h1, l0, l1);
    uint32_t* hw = (uint32_t*)(hh + (size_t)row * DM);
    uint32_t* lw = (uint32_t*)(hl + (size_t)row * DM);
    hw[2 * t] = h0; hw[2 * t + 1] = h1;
    lw[2 * t] = l0; lw[2 * t + 1] = l1;
}

// ===========================================================================
// Weight split: fp32 -> bf16 hi/lo
// ===========================================================================
__global__ __launch_bounds__(256) void split_kernel(const float* __restrict__ src,
                                                    __nv_bfloat16* __restrict__ hi,
                                                    __nv_bfloat16* __restrict__ lo,
                                                    int n4) {
    int i = blockIdx.x * blockDim.x + threadIdx.x;
    if (i >= n4) return;
    float4 v = ((const float4*)src)[i];
    uint32_t h0, h1, l0, l1;
    split4(v, h0, h1, l0, l1);
    ((uint32_t*)hi)[2 * i] = h0; ((uint32_t*)hi)[2 * i + 1] = h1;
    ((uint32_t*)lo)[2 * i] = l0; ((uint32_t*)lo)[2 * i + 1] = l1;
}

// ===========================================================================
// Split-bf16 NT GEMM, pre-split bf16 inputs, cp.async staging + ldmatrix.
// 2 CTAs/SM (launch_bounds), single barrier per stage, copy/compute overlap.
// ===========================================================================
#define BM 128
#define BN 128
#define SROW 12
#define SARR (BM * SROW)              // 1536 u32
#define SSTAGE (4 * SARR)
#define GEMM_SMEM (2 * SSTAGE * 4)    // 49152 B

__global__ __launch_bounds__(256, 2) void gemm_bf(
    const __nv_bfloat16* __restrict__ Ah, const __nv_bfloat16* __restrict__ Al,
    const __nv_bfloat16* __restrict__ Bh, const __nv_bfloat16* __restrict__ Bl,
    float* __restrict__ C, int M, int N_, int K) {
    extern __shared__ uint32_t smu[];
    int t = threadIdx.x;
    int lane = t & 31, wid = t >> 5;
    int wm = wid >> 2, wn = wid & 3;
    int g = lane >> 2, t4 = lane & 3;
    int m0 = blockIdx.y * BM, n0 = blockIdx.x * BN;

    float acc[4][4][4];
    #pragma unroll
    for (int i = 0; i < 4; i++)
        #pragma unroll
        for (int j = 0; j < 4; j++)
            #pragma unroll
            for (int q = 0; q < 4; q++) acc[i][j][q] = 0.f;

    // staging indexing: thread -> row t>>1, k-half t&1 (8 bf16 = 16B each)
    int lrow = t >> 1, lhalf = t & 1;
    uint32_t sbase = smem_u32addr(smu);
    uint32_t sdst = sbase + (lrow * SROW + lhalf * 4) * 4;
    const __nv_bfloat16* ap = Ah + (size_t)(m0 + lrow) * K + lhalf * 8;
    const __nv_bfloat16* alp = Al + (size_t)(m0 + lrow) * K + lhalf * 8;
    const __nv_bfloat16* bp = Bh + (size_t)(n0 + lrow) * K + lhalf * 8;
    const __nv_bfloat16* blp = Bl + (size_t)(n0 + lrow) * K + lhalf * 8;

    const int NST = K / 16;
    // prologue: stage 0
    cp16(sdst,                ap);
    cp16(sdst + SARR * 4,     alp);
    cp16(sdst + 2 * SARR * 4, bp);
    cp16(sdst + 3 * SARR * 4, blp);
    CP_COMMIT();

    // ldmatrix lane byte offsets
    int r8 = lane & 7, mat = lane >> 3;
    int a_loff = ((wm * 64 + (mat & 1) * 8 + r8) * SROW + (mat >> 1) * 4) * 4;
    int b_loff = ((wn * 32 + (mat >> 1) * 8 + r8) * SROW + (mat & 1) * 4) * 4;

    for (int s = 0; s < NST; s++) {
        CP_WAIT0();
        __syncthreads();
        if (s + 1 < NST) {
            int k0 = (s + 1) * 16;
            uint32_t db = sbase + ((s + 1) & 1) * (SSTAGE * 4) +
                          (lrow * SROW + lhalf * 4) * 4;
            cp16(db,                ap + k0);
            cp16(db + SARR * 4,     alp + k0);
            cp16(db + 2 * SARR * 4, bp + k0);
            cp16(db + 3 * SARR * 4, blp + k0);
            CP_COMMIT();
        }

        uint32_t stb = sbase + (s & 1) * (SSTAGE * 4);
        // B fragments resident for the stage
        uint32_t bh[4][2], bl[4][2];
        #pragma unroll
        for (int p = 0; p < 2; p++) {
            ldmx4(bh[2 * p][0], bh[2 * p][1], bh[2 * p + 1][0], bh[2 * p + 1][1],
                  stb + 2 * SARR * 4 + b_loff + p * (16 * SROW * 4));
            ldmx4(bl[2 * p][0], bl[2 * p][1], bl[2 * p + 1][0], bl[2 * p + 1][1],
                  stb + 3 * SARR * 4 + b_loff + p * (16 * SROW * 4));
        }
        // A fragments per mb (keeps live registers low)
        #pragma unroll
        for (int mb = 0; mb < 4; mb++) {
            uint32_t ah[4], al[4];
            ldmx4(ah[0], ah[1], ah[2], ah[3],
                  stb + a_loff + mb * (16 * SROW * 4));
            ldmx4(al[0], al[1], al[2], al[3],
                  stb + SARR * 4 + a_loff + mb * (16 * SROW * 4));
            #pragma unroll
            for (int nb = 0; nb < 4; nb++) {
                mma_bf16(acc[mb][nb], ah, bh[nb]);
                mma_bf16(acc[mb][nb], ah, bl[nb]);
                mma_bf16(acc[mb][nb], al, bh[nb]);
            }
        }
    }

    #pragma unroll
    for (int mb = 0; mb < 4; mb++) {
        int row = m0 + wm * 64 + mb * 16 + g;
        #pragma unroll
        for (int nb = 0; nb < 4; nb++) {
            int col = n0 + wn * 32 + nb * 8 + 2 * t4;
            *(float2*)(C + (size_t)row * N_ + col) =
                make_float2(acc[mb][nb][0], acc[mb][nb][1]);
            *(float2*)(C + (size_t)(row + 8) * N_ + col) =
                make_float2(acc[mb][nb][2], acc[mb][nb][3]);
        }
    }
}

// ===========================================================================
// RoPE (unchanged)
// ===========================================================================
__global__ __launch_bounds__(512) void rope_kernel(float* __restrict__ qkv) {
    int token = blockIdx.x;
    int p = threadIdx.x;
    int head = p >> 5;
    int i = p & 31;
    int l = token & (LSEQ - 1);
    double inv = pow(10000.0, -(double)i / 32.0);
    double ang = (double)l * inv;
    double snd, csd;
    sincos(ang, &snd, &csd);
    float sn = (float)snd, cs = (float)csd;
    size_t base = (size_t)token * 3 * DM + head * DK + 2 * i;
    float x1 = qkv[base], x2 = qkv[base + 1];
    qkv[base]     = x1 * cs - x2 * sn;
    qkv[base + 1] = x1 * sn + x2 * cs;
    float y1 = qkv[base + DM], y2 = qkv[base + DM + 1];
    qkv[base + DM]     = y1 * cs - y2 * sn;
    qkv[base + DM + 1] = y1 * sn + y2 * cs;
}

// ===========================================================================
// Tensor-core causal flash attention (split-bf16 mma.sync, FA2-style).
// Epilogue writes bf16 hi/lo split for the out-projection GEMM.
// ===========================================================================
#define FQ 128
#define FK 64
#define FR 36
#define OQH 0
#define OQL (FQ * FR)
#define OKH (2 * FQ * FR)
#define OKL (OKH + FK * FR)
#define OVH (OKH + 2 * FK * FR)
#define OVL (OVH + FK * FR)
#define FLASH_SMEM ((2 * FQ * FR + 4 * FK * FR) * 4)

__global__ __launch_bounds__(256) void flash_tc(const float* __restrict__ qkv,
                                                __nv_bfloat16* __restrict__ oh,
                                                __nv_bfloat16* __restrict__ ol) {
    extern __shared__ uint32_t su[];
    int t = threadIdx.x;
    int lane = t & 31, wq = t >> 5;
    int g = lane >> 2, t4 = lane & 3;
    int qt = (int)gridDim.x - 1 - (int)blockIdx.x;
    int h = blockIdx.y, b = blockIdx.z;
    int qbase = qt * FQ;

    {
        const float* qb = qkv + ((size_t)(b * LSEQ + qbase)) * 3 * DM + h * DK;
        #pragma unroll
        for (int it = 0; it < 8; it++) {
            int f = t + it * 256;
            int row = f >> 4, c4 = (f & 15);
            float4 v = *(const float4*)(qb + (size_t)row * 3 * DM + c4 * 4);
            uint32_t h0, h1, l0, l1;
            split4(v, h0, h1, l0, l1);
            int idx = row * FR + c4 * 2;
            su[OQH + idx] = h0; su[OQH + idx + 1] = h1;
            su[OQL + idx] = l0; su[OQL + idx + 1] = l1;
        }
    }
    __syncthreads();

    uint32_t qah[4][4], qal[4][4];
    #pragma unroll
    for (int s = 0; s < 4; s++) {
        int idx = (wq * 16 + g) * FR + 8 * s + t4;
        qah[s][0] = su[OQH + idx];          qah[s][1] = su[OQH + idx + 8 * FR];
        qah[s][2] = su[OQH + idx + 4];      qah[s][3] = su[OQH + idx + 8 * FR + 4];
        qal[s][0] = su[OQL + idx];          qal[s][1] = su[OQL + idx + 8 * FR];
        qal[s][2] = su[OQL + idx + 4];      qal[s][3] = su[OQL + idx + 8 * FR + 4];
    }

    float of[8][4];
    #pragma unroll
    for (int n = 0; n < 8; n++)
        #pragma unroll
        for (int c = 0; c < 4; c++) of[n][c] = 0.f;
    float m0 = -1e30f, m1 = -1e30f, l0 = 0.f, l1 = 0.f;

    uint32_t vbase_h = smem_u32addr(su + OVH);
    uint32_t vbase_l = smem_u32addr(su + OVL);
    int voff = ((lane & 15) * FR + (lane >> 4) * 4) * 4;

    int row0 = qbase + wq * 16 + g;
    int nkt = 2 * qt + 2;

    for (int kt = 0; kt < nkt; kt++) {
        {
            const float* kb = qkv + ((size_t)(b * LSEQ + kt * FK)) * 3 * DM + DM + h * DK;
            #pragma unroll
            for (int it = 0; it < 4; it++) {
                int f = t + it * 256;
                int row = f >> 4, c4 = (f & 15);
                int idx = row * FR + c4 * 2;
                float4 kv = *(const float4*)(kb + (size_t)row * 3 * DM + c4 * 4);
                uint32_t h0, h1, lo0, lo1;
                split4(kv, h0, h1, lo0, lo1);
                su[OKH + idx] = h0; su[OKH + idx + 1] = h1;
                su[OKL + idx] = lo0; su[OKL + idx + 1] = lo1;
                float4 vv = *(const float4*)(kb + DM + (size_t)row * 3 * DM + c4 * 4);
                split4(vv, h0, h1, lo0, lo1);
                su[OVH + idx] = h0; su[OVH + idx + 1] = h1;
                su[OVL + idx] = lo0; su[OVL + idx + 1] = lo1;
            }
        }
        __syncthreads();

        int ktb = kt * FK;
        bool active = (ktb <= qbase + wq * 16);
        if (active) {
            float sf[8][4];
            #pragma unroll
            for (int j = 0; j < 8; j++)
                #pragma unroll
                for (int c = 0; c < 4; c++) sf[j][c] = 0.f;
            #pragma unroll
            for (int s = 0; s < 4; s++) {
                #pragma unroll
                for (int j = 0; j < 8; j++) {
                    int idx = (8 * j + g) * FR + 8 * s + t4;
                    uint32_t kb2[2], kl2[2];
                    kb2[0] = su[OKH + idx]; kb2[1] = su[OKH + idx + 4];
                    kl2[0] = su[OKL + idx]; kl2[1] = su[OKL + idx + 4];
                    mma_bf16(sf[j], qah[s], kb2);
                    mma_bf16(sf[j], qal[s], kb2);
                    mma_bf16(sf[j], qah[s], kl2);
                }
            }

            const float scale = 0.125f;
            bool need_mask = (ktb + FK - 1 > qbase + wq * 16);
            #pragma unroll
            for (int j = 0; j < 8; j++) {
                int col = ktb + 8 * j + 2 * t4;
                #pragma unroll
                for (int c = 0; c < 4; c++) {
                    float v = sf[j][c] * scale;
                    if (need_mask) {
                        int cc = col + (c & 1);
                        int rr = row0 + (c >> 1) * 8;
                        if (cc > rr) v = -1e30f;
                    }
                    sf[j][c] = v;
                }
            }

            float mx0 = -1e30f, mx1 = -1e30f;
            #pragma unroll
            for (int j = 0; j < 8; j++) {
                mx0 = fmaxf(mx0, fmaxf(sf[j][0], sf[j][1]));
                mx1 = fmaxf(mx1, fmaxf(sf[j][2], sf[j][3]));
            }
            mx0 = fmaxf(mx0, __shfl_xor_sync(0xffffffffu, mx0, 1));
            mx0 = fmaxf(mx0, __shfl_xor_sync(0xffffffffu, mx0, 2));
            mx1 = fmaxf(mx1, __shfl_xor_sync(0xffffffffu, mx1, 1));
            mx1 = fmaxf(mx1, __shfl_xor_sync(0xffffffffu, mx1, 2));
            float mn0 = fmaxf(m0, mx0), mn1 = fmaxf(m1, mx1);
            float a0 = __expf(m0 - mn0), a1 = __expf(m1 - mn1);
            m0 = mn0; m1 = mn1;
            float s0 = 0.f, s1 = 0.f;
            #pragma unroll
            for (int j = 0; j < 8; j++) {
                sf[j][0] = __expf(sf[j][0] - m0);
                sf[j][1] = __expf(sf[j][1] - m0);
                sf[j][2] = __expf(sf[j][2] - m1);
                sf[j][3] = __expf(sf[j][3] - m1);
                s0 += sf[j][0] + sf[j][1];
                s1 += sf[j][2] + sf[j][3];
            }
            s0 += __shfl_xor_sync(0xffffffffu, s0, 1);
            s0 += __shfl_xor_sync(0xffffffffu, s0, 2);
            s1 += __shfl_xor_sync(0xffffffffu, s1, 1);
            s1 += __shfl_xor_sync(0xffffffffu, s1, 2);
            l0 = l0 * a0 + s0;
            l1 = l1 * a1 + s1;
            #pragma unroll
            for (int n = 0; n < 8; n++) {
                of[n][0] *= a0; of[n][1] *= a0;
                of[n][2] *= a1; of[n][3] *= a1;
            }

            #pragma unroll
            for (int s = 0; s < 4; s++) {
                uint32_t pah[4], pal[4];
                #pragma unroll
                for (int half = 0; half < 2; half++) {
                    float p0 = sf[2 * s + half][0], p1 = sf[2 * s + half][1];
                    float p2 = sf[2 * s + half][2], p3 = sf[2 * s + half][3];
                    __nv_bfloat16 h0 = __float2bfloat16_rn(p0);
                    __nv_bfloat16 h1b = __float2bfloat16_rn(p1);
                    __nv_bfloat16 h2 = __float2bfloat16_rn(p2);
                    __nv_bfloat16 h3 = __float2bfloat16_rn(p3);
                    pah[2 * half]     = pack2(h0, h1b);
                    pah[2 * half + 1] = pack2(h2, h3);
                    pal[2 * half]     = pack2(
                        __float2bfloat16_rn(p0 - __bfloat162float(h0)),
                        __float2bfloat16_rn(p1 - __bfloat162float(h1b)));
                    pal[2 * half + 1] = pack2(
                        __float2bfloat16_rn(p2 - __bfloat162float(h2)),
                        __float2bfloat16_rn(p3 - __bfloat162float(h3)));
                }
                #pragma unroll
                for (int j2 = 0; j2 < 4; j2++) {
                    uint32_t vh0, vh1, vh2, vh3, vl0, vl1, vl2, vl3;
                    uint32_t boff2 = (16 * s * FR + 8 * j2) * 4 + voff;
                    ldmx4t(vh0, vh1, vh2, vh3, vbase_h + boff2);
                    ldmx4t(vl0, vl1, vl2, vl3, vbase_l + boff2);
                    uint32_t bh0[2] = {vh0, vh1}, bh1[2] = {vh2, vh3};
                    uint32_t bl0[2] = {vl0, vl1}, bl1[2] = {vl2, vl3};
                    mma_bf16(of[2 * j2], pah, bh0);
                    mma_bf16(of[2 * j2], pal, bh0);
                    mma_bf16(of[2 * j2], pah, bl0);
                    mma_bf16(of[2 * j2 + 1], pah, bh1);
                    mma_bf16(of[2 * j2 + 1], pal, bh1);
                    mma_bf16(of[2 * j2 + 1], pah, bl1);
                }
            }
        }
        __syncthreads();
    }

    // ---- epilogue: write bf16 hi/lo split ----
    float i0 = 1.f / l0, i1 = 1.f / l1;
    size_t base0 = (size_t)(b * LSEQ + row0) * DM + h * DK;
    size_t base1 = base0 + 8 * DM;
    uint32_t* ohw = (uint32_t*)oh;
    uint32_t* olw = (uint32_t*)ol;
    #pragma unroll
    for (int n = 0; n < 8; n++) {
        int col = 8 * n + 2 * t4;
        float v0 = of[n][0] * i0, v1 = of[n][1] * i0;
        float v2 = of[n][2] * i1, v3 = of[n][3] * i1;
        __nv_bfloat16 h0 = __float2bfloat16_rn(v0);
        __nv_bfloat16 h1 = __float2bfloat16_rn(v1);
        __nv_bfloat16 h2 = __float2bfloat16_rn(v2);
        __nv_bfloat16 h3 = __float2bfloat16_rn(v3);
        ohw[(base0 + col) >> 1] = pack2(h0, h1);
        ohw[(base1 + col) >> 1] = pack2(h2, h3);
        olw[(base0 + col) >> 1] = pack2(
            __float2bfloat16_rn(v0 - __bfloat162float(h0)),
            __float2bfloat16_rn(v1 - __bfloat162float(h1)));
        olw[(base1 + col) >> 1] = pack2(
            __float2bfloat16_rn(v2 - __bfloat162float(h2)),
            __float2bfloat16_rn(v3 - __bfloat162float(h3)));
    }
}

// ===========================================================================
extern "C" void kernel_launch(void* const* d_in, const int* in_sizes, int n_in,
                              void* d_out, int out_size) {
    const float* x    = (const float*)d_in[0];
    const float* W_in = (const float*)d_in[1];
    const float* W_o  = (const float*)d_in[2];
    float* out = (float*)d_out;

    float* qkv;
    __nv_bfloat16 *hh, *hl, *wih, *wil, *woh, *wol, *oh, *ol;
    cudaGetSymbolAddress((void**)&qkv, g_qkv);
    cudaGetSymbolAddress((void**)&hh,  g_hh);
    cudaGetSymbolAddress((void**)&hl,  g_hl);
    cudaGetSymbolAddress((void**)&wih, g_wih);
    cudaGetSymbolAddress((void**)&wil, g_wil);
    cudaGetSymbolAddress((void**)&woh, g_woh);
    cudaGetSymbolAddress((void**)&wol, g_wol);
    cudaGetSymbolAddress((void**)&oh,  g_oh);
    cudaGetSymbolAddress((void**)&ol,  g_ol);

    cudaFuncSetAttribute(gemm_bf, cudaFuncAttributeMaxDynamicSharedMemorySize,
                         GEMM_SMEM);
    cudaFuncSetAttribute(flash_tc, cudaFuncAttributeMaxDynamicSharedMemorySize,
                         FLASH_SMEM);

    ln_kernel<<<TOKENS, 256>>>(x, hh, hl);
    split_kernel<<<(3 * DM * DM / 4 + 255) / 256, 256>>>(W_in, wih, wil,
                                                         3 * DM * DM / 4);
    split_kernel<<<(DM * DM / 4 + 255) / 256, 256>>>(W_o, woh, wol,
                                                     DM * DM / 4);

    dim3 g1(3 * DM / BN, TOKENS / BM);
    gemm_bf<<<g1, 256, GEMM_SMEM>>>(hh, hl, wih, wil, qkv, TOKENS, 3 * DM, DM);

    rope_kernel<<<TOKENS, 512>>>(qkv);

    dim3 g2(LSEQ / FQ, NH, NB);
    flash_tc<<<g2, 256, FLASH_SMEM>>>(qkv, oh, ol);

    dim3 g3(DM / BN, TOKENS / BM);
    gemm_bf<<<g3, 256, GEMM_SMEM>>>(oh, ol, woh, wol, out, TOKENS, DM, DM);
}